// round 1
// baseline (speedup 1.0000x reference)
#include <cuda_runtime.h>
#include <cstdint>

// Problem constants (fixed shapes)
#define B_  4
#define T_  8192
#define D_  1024
#define L_  128
#define H_  16
#define R_  (B_*T_)      // 32768 rows
#define NKQV 1280        // K(128) | Q(128) | V(1024)

// ---------------- scratch (device globals; allocation-free rule) -------------
__device__ float g_Xr  [R_ * D_];       // tf32-rounded X          (128 MB)
__device__ float g_KQV [R_ * NKQV];     // K|Q|V projections       (160 MB)
__device__ float g_Wcat[D_ * NKQV];     // packed tf32 weights     (5 MB)
__device__ float g_Po  [D_ * D_];       // tf32 o_proj             (4 MB)
__device__ float g_y   [R_ * D_];       // attention output (tf32) (128 MB)
__device__ float g_Kv  [B_*H_*8*64];    // KV state
__device__ float g_Ksum[B_*H_*8];

// ---------------- helpers ----------------------------------------------------
__device__ __forceinline__ float tf32r(float x){
    uint32_t u; asm("cvt.rna.tf32.f32 %0, %1;" : "=r"(u) : "f"(x));
    return __uint_as_float(u);
}

__device__ __forceinline__ void cp16(float* dst, const float* src){
    uint32_t d = (uint32_t)__cvta_generic_to_shared(dst);
    asm volatile("cp.async.cg.shared.global [%0], [%1], 16;" :: "r"(d), "l"(src));
}

__device__ __forceinline__ void mma8(float* c,
    uint32_t a0, uint32_t a1, uint32_t a2, uint32_t a3,
    uint32_t b0, uint32_t b1){
    asm volatile("mma.sync.aligned.m16n8k8.row.col.f32.tf32.tf32.f32 "
                 "{%0,%1,%2,%3}, {%4,%5,%6,%7}, {%8,%9}, {%0,%1,%2,%3};"
                 : "+f"(c[0]), "+f"(c[1]), "+f"(c[2]), "+f"(c[3])
                 : "r"(a0), "r"(a1), "r"(a2), "r"(a3), "r"(b0), "r"(b1));
}

// ---------------- prologue kernels -------------------------------------------
__global__ void prep_weights_kernel(const float* __restrict__ Wk,
                                    const float* __restrict__ Wq,
                                    const float* __restrict__ Wv,
                                    const float* __restrict__ Po){
    int i = blockIdx.x * blockDim.x + threadIdx.x;
    if (i < D_ * NKQV){
        int k = i / NKQV, n = i % NKQV;
        float v = (n < 128) ? Wk[k*L_ + n]
                : (n < 256) ? Wq[k*L_ + (n-128)]
                            : Wv[k*D_ + (n-256)];
        g_Wcat[i] = tf32r(v);
    }
    if (i < D_ * D_) g_Po[i] = tf32r(Po[i]);
}

__global__ void round_x_kernel(const float4* __restrict__ X){
    int i = blockIdx.x * blockDim.x + threadIdx.x;  // over R_*D_/4 = 8388608
    float4 v = X[i];
    v.x = tf32r(v.x); v.y = tf32r(v.y); v.z = tf32r(v.z); v.w = tf32r(v.w);
    reinterpret_cast<float4*>(g_Xr)[i] = v;
}

__global__ void zero_state_kernel(){
    int i = blockIdx.x * blockDim.x + threadIdx.x;
    if (i < B_*H_*8*64) g_Kv[i] = 0.f;
    if (i < B_*H_*8)    g_Ksum[i] = 0.f;
}

// ---------------- tf32 GEMM: C[M,N] = A[M,K(lda=K)] @ Bm[K,N(ldb=N)] ---------
// BM=128, BN=128, BK=16; 256 threads, 8 warps (2x4), each 64x32; m16n8k8 tf32.
__global__ __launch_bounds__(256)
void gemm_tf32_kernel(const float* __restrict__ A, const float* __restrict__ Bm,
                      float* __restrict__ C, int N, int K){
    __shared__ float As[2][128*20];   // pad BK 16->20 (conflict-free frag loads)
    __shared__ float Bs[2][16*136];   // pad BN 128->136

    const int tid = threadIdx.x;
    const int bm = blockIdx.y * 128;
    const int bn = blockIdx.x * 128;

    const int ar = tid >> 2;          // 0..63
    const int ac = (tid & 3) << 2;    // 0,4,8,12
    const int br = tid >> 5;          // 0..7
    const int bc = (tid & 31) << 2;   // 0..124

    const float* Ag = A  + (size_t)(bm + ar) * K + ac;
    const float* Bg = Bm + (size_t)br * N + bn + bc;

    const int w    = tid >> 5;
    const int wm   = (w >> 2) * 64;
    const int wn   = (w & 3) * 32;
    const int lane = tid & 31;
    const int gr   = lane >> 2;
    const int gc   = lane & 3;

    float c[4][4][4];
    #pragma unroll
    for (int a = 0; a < 4; a++)
        #pragma unroll
        for (int b = 0; b < 4; b++)
            #pragma unroll
            for (int e = 0; e < 4; e++) c[a][b][e] = 0.f;

    // prefetch tile 0
    cp16(&As[0][ar*20 + ac],        Ag);
    cp16(&As[0][(ar+64)*20 + ac],   Ag + (size_t)64*K);
    cp16(&Bs[0][br*136 + bc],       Bg);
    cp16(&Bs[0][(br+8)*136 + bc],   Bg + (size_t)8*N);
    asm volatile("cp.async.commit_group;" ::: "memory");

    const int KT = K >> 4;
    for (int kt = 0; kt < KT; ++kt){
        const int buf = kt & 1;
        if (kt + 1 < KT){
            const float* a0 = Ag + (kt+1)*16;
            const float* b0 = Bg + (size_t)(kt+1)*16*N;
            cp16(&As[buf^1][ar*20 + ac],      a0);
            cp16(&As[buf^1][(ar+64)*20 + ac], a0 + (size_t)64*K);
            cp16(&Bs[buf^1][br*136 + bc],     b0);
            cp16(&Bs[buf^1][(br+8)*136 + bc], b0 + (size_t)8*N);
            asm volatile("cp.async.commit_group;" ::: "memory");
            asm volatile("cp.async.wait_group 1;" ::: "memory");
        } else {
            asm volatile("cp.async.wait_group 0;" ::: "memory");
        }
        __syncthreads();

        const float* as = As[buf];
        const float* bs = Bs[buf];
        #pragma unroll
        for (int ks = 0; ks < 16; ks += 8){
            uint32_t af[4][4], bf[4][2];
            #pragma unroll
            for (int mi = 0; mi < 4; ++mi){
                int rb = wm + mi*16 + gr;
                af[mi][0] = __float_as_uint(as[rb*20     + ks + gc]);
                af[mi][1] = __float_as_uint(as[(rb+8)*20 + ks + gc]);
                af[mi][2] = __float_as_uint(as[rb*20     + ks + gc + 4]);
                af[mi][3] = __float_as_uint(as[(rb+8)*20 + ks + gc + 4]);
            }
            #pragma unroll
            for (int ni = 0; ni < 4; ++ni){
                int cb = wn + ni*8 + gr;
                bf[ni][0] = __float_as_uint(bs[(ks+gc)*136   + cb]);
                bf[ni][1] = __float_as_uint(bs[(ks+gc+4)*136 + cb]);
            }
            #pragma unroll
            for (int mi = 0; mi < 4; ++mi)
                #pragma unroll
                for (int ni = 0; ni < 4; ++ni)
                    mma8(c[mi][ni], af[mi][0], af[mi][1], af[mi][2], af[mi][3],
                         bf[ni][0], bf[ni][1]);
        }
        __syncthreads();
    }

    #pragma unroll
    for (int mi = 0; mi < 4; ++mi)
        #pragma unroll
        for (int ni = 0; ni < 4; ++ni){
            int r0 = bm + wm + mi*16 + gr;
            int c0 = bn + wn + ni*8 + gc*2;
            *reinterpret_cast<float2*>(&C[(size_t)r0*N + c0])     =
                make_float2(c[mi][ni][0], c[mi][ni][1]);
            *reinterpret_cast<float2*>(&C[(size_t)(r0+8)*N + c0]) =
                make_float2(c[mi][ni][2], c[mi][ni][3]);
        }
}

// ---------------- E = exp(K) * mask (in place, K region of g_KQV) ------------
__global__ void exp_mask_kernel(const float* __restrict__ mask){
    int i = blockIdx.x * blockDim.x + threadIdx.x;   // over R_*128
    int r = i >> 7, j = i & 127;
    float m = mask[r];
    float* p = &g_KQV[(size_t)r * NKQV + j];
    *p = __expf(*p) * m;
}

// ---------------- Kv[b,h,l,d] = sum_t E[t,l] * (V[t,d]*m); Ksum = sum_t E ----
__global__ __launch_bounds__(256)
void kv_accum_kernel(const float* __restrict__ mask){
    int bh = blockIdx.x >> 4;       // 0..63  (b*16+h)
    int tc = blockIdx.x & 15;       // T chunk
    int b  = bh >> 4, h = bh & 15;
    int tid = threadIdx.x;
    int d  = tid & 63;
    int ls = tid >> 6;              // 0..3
    int l0 = ls*2, l1 = ls*2 + 1;

    __shared__ float Vs[16][64];
    __shared__ float Es[16][8];

    float acc0 = 0.f, acc1 = 0.f, ks0 = 0.f, ks1 = 0.f;
    const int rowbase = b * T_;
    const int t0 = tc * (T_/16);

    for (int it = 0; it < (T_/16)/16; ++it){     // 32 sub-iters of 16 t each
        int tb = t0 + it*16;
        #pragma unroll
        for (int q = 0; q < 4; ++q){
            int vi = q*256 + tid;
            int tt = vi >> 6, dd = vi & 63;
            int row = rowbase + tb + tt;
            Vs[tt][dd] = g_KQV[(size_t)row*NKQV + 256 + h*64 + dd] * mask[row];
        }
        if (tid < 128){
            int tt = tid >> 3, l = tid & 7;
            Es[tt][l] = g_KQV[(size_t)(rowbase + tb + tt)*NKQV + h*8 + l];
        }
        __syncthreads();
        #pragma unroll
        for (int tt = 0; tt < 16; ++tt){
            float v = Vs[tt][d];
            float e0 = Es[tt][l0], e1 = Es[tt][l1];
            acc0 += e0 * v;
            acc1 += e1 * v;
            if (d == 0){ ks0 += e0; ks1 += e1; }
        }
        __syncthreads();
    }
    atomicAdd(&g_Kv[(bh*8 + l0)*64 + d], acc0);
    atomicAdd(&g_Kv[(bh*8 + l1)*64 + d], acc1);
    if (d == 0){
        atomicAdd(&g_Ksum[bh*8 + l0], ks0);
        atomicAdd(&g_Ksum[bh*8 + l1], ks1);
    }
}

// ---------------- y = softmax(Q) @ (Kv/Ksum), tf32-rounded -------------------
__global__ __launch_bounds__(256)
void y_kernel(){
    int rb = blockIdx.x * 16;       // 16 rows per block
    int b  = rb >> 13;              // row / 8192
    int tid = threadIdx.x;

    __shared__ float Kvn[H_*8*64];  // 32 KB
    __shared__ float Qs[16][128];   // 8 KB

    for (int i = tid; i < H_*8*64; i += 256)
        Kvn[i] = g_Kv[b*(H_*8*64) + i] / g_Ksum[b*(H_*8) + (i >> 6)];

    {   // per-(row,head) softmax over l=8
        int rl = tid >> 4, h = tid & 15;
        const float* q = &g_KQV[(size_t)(rb + rl)*NKQV + 128 + h*8];
        float v[8]; float mx = -1e30f;
        #pragma unroll
        for (int j = 0; j < 8; ++j){ v[j] = q[j]; mx = fmaxf(mx, v[j]); }
        float s = 0.f;
        #pragma unroll
        for (int j = 0; j < 8; ++j){ v[j] = __expf(v[j] - mx); s += v[j]; }
        float inv = 1.f / s;
        #pragma unroll
        for (int j = 0; j < 8; ++j) Qs[rl][h*8 + j] = v[j] * inv;
    }
    __syncthreads();

    #pragma unroll
    for (int cq = 0; cq < 4; ++cq){
        int col = cq*256 + tid;
        int h = col >> 6, d = col & 63;
        float kv[8];
        #pragma unroll
        for (int l = 0; l < 8; ++l) kv[l] = Kvn[(h*8 + l)*64 + d];
        #pragma unroll
        for (int r = 0; r < 16; ++r){
            float y = 0.f;
            #pragma unroll
            for (int l = 0; l < 8; ++l) y += Qs[r][h*8 + l] * kv[l];
            g_y[(size_t)(rb + r)*D_ + col] = tf32r(y);
        }
    }
}

// ---------------- launch -----------------------------------------------------
extern "C" void kernel_launch(void* const* d_in, const int* in_sizes, int n_in,
                              void* d_out, int out_size){
    const float* X    = (const float*)d_in[0];
    const float* mask = (const float*)d_in[1];
    const float* Wk   = (const float*)d_in[2];
    const float* Wq   = (const float*)d_in[3];
    const float* Wv   = (const float*)d_in[4];
    const float* Po   = (const float*)d_in[5];
    float* out = (float*)d_out;

    void *pXr, *pKQV, *pWcat, *pPo, *pY;
    cudaGetSymbolAddress(&pXr,   g_Xr);
    cudaGetSymbolAddress(&pKQV,  g_KQV);
    cudaGetSymbolAddress(&pWcat, g_Wcat);
    cudaGetSymbolAddress(&pPo,   g_Po);
    cudaGetSymbolAddress(&pY,    g_y);

    prep_weights_kernel<<<5120, 256>>>(Wk, Wq, Wv, Po);
    round_x_kernel<<<(R_*D_/4)/256, 256>>>((const float4*)X);
    zero_state_kernel<<<(B_*H_*8*64 + 255)/256, 256>>>();

    dim3 g1(NKQV/128, R_/128);   // (10, 256)
    gemm_tf32_kernel<<<g1, 256>>>((const float*)pXr, (const float*)pWcat,
                                  (float*)pKQV, NKQV, D_);

    exp_mask_kernel<<<(R_*128)/256, 256>>>(mask);
    kv_accum_kernel<<<B_*H_*16, 256>>>(mask);
    y_kernel<<<R_/16, 256>>>();

    dim3 g2(D_/128, R_/128);     // (8, 256)
    gemm_tf32_kernel<<<g2, 256>>>((const float*)pY, (const float*)pPo,
                                  out, D_, D_);
}

// round 2
// speedup vs baseline: 1.3684x; 1.3684x over previous
#include <cuda_runtime.h>
#include <cstdint>

// Problem constants (fixed shapes)
#define B_  4
#define T_  8192
#define D_  1024
#define L_  128
#define H_  16
#define R_  (B_*T_)      // 32768 rows
#define NKQV 1280        // K(128) | Q(128) | V(1024)

// ---------------- scratch (device globals; allocation-free rule) -------------
// A-side operands stored in mma "fragment order":
//   [m_block128][k_tile8][m_sub16 (8)][lane (32)][4]   (1024 floats / (mb,kt))
// B-side operands:
//   [n_block128][k_tile8][n_sub8 (16)][lane (32)][2]
__device__ float g_Xa  [R_ * D_];       // packed tf32 X             (128 MB)
__device__ float g_KQV [R_ * NKQV];     // K|Q|V projections         (160 MB)
__device__ float g_Wcat[D_ * NKQV];     // packed tf32 [Wk|Wq|Wv]    (5 MB)
__device__ float g_Pop [D_ * D_];       // packed tf32 o_proj        (4 MB)
__device__ float g_ya  [R_ * D_];       // attention out, packed     (128 MB)
__device__ float g_Kv  [B_*H_*8*64];
__device__ float g_Ksum[B_*H_*8];

// ---------------- helpers ----------------------------------------------------
__device__ __forceinline__ float tf32r(float x){
    uint32_t u; asm("cvt.rna.tf32.f32 %0, %1;" : "=r"(u) : "f"(x));
    return __uint_as_float(u);
}

__device__ __forceinline__ void cp16(float* dst, const float* src){
    uint32_t d = (uint32_t)__cvta_generic_to_shared(dst);
    asm volatile("cp.async.cg.shared.global [%0], [%1], 16;" :: "r"(d), "l"(src));
}

__device__ __forceinline__ void mma8(float* c,
    uint32_t a0, uint32_t a1, uint32_t a2, uint32_t a3,
    uint32_t b0, uint32_t b1){
    asm volatile("mma.sync.aligned.m16n8k8.row.col.f32.tf32.tf32.f32 "
                 "{%0,%1,%2,%3}, {%4,%5,%6,%7}, {%8,%9}, {%0,%1,%2,%3};"
                 : "+f"(c[0]), "+f"(c[1]), "+f"(c[2]), "+f"(c[3])
                 : "r"(a0), "r"(a1), "r"(a2), "r"(a3), "r"(b0), "r"(b1));
}

// packed A index for element (m, k)
__device__ __forceinline__ size_t pkA(int m, int k){
    int mb = m >> 7, msub = (m >> 4) & 7, r16 = m & 15;
    int rowbit = r16 >> 3, gr = r16 & 7;
    int kt = k >> 3, kk = k & 7, gc = kk & 3, c4 = kk >> 2;
    return ((size_t)(mb*128 + kt))*1024 + msub*128 + (gr*4 + gc)*4 + ((c4<<1)|rowbit);
}
// packed B index for element (k, n)
__device__ __forceinline__ size_t pkB(int k, int n){
    int nb = n >> 7, nl = n & 127, nsub = nl >> 3, gr = nl & 7;
    int kt = k >> 3, kk = k & 7, gc = kk & 3, j = kk >> 2;
    return ((size_t)(nb*128 + kt))*1024 + nsub*64 + (gr*4 + gc)*2 + j;
}

// ---------------- prologue kernels -------------------------------------------
__global__ void prep_weights_kernel(const float* __restrict__ Wk,
                                    const float* __restrict__ Wq,
                                    const float* __restrict__ Wv,
                                    const float* __restrict__ Po){
    int i = blockIdx.x * blockDim.x + threadIdx.x;
    if (i < D_ * NKQV){
        int k = i / NKQV, n = i - k * NKQV;
        float v = (n < 128) ? Wk[k*L_ + n]
                : (n < 256) ? Wq[k*L_ + (n-128)]
                            : Wv[k*D_ + (n-256)];
        g_Wcat[pkB(k, n)] = tf32r(v);
    }
    if (i < D_ * D_){
        int k = i >> 10, n = i & 1023;
        g_Pop[pkB(k, n)] = tf32r(Po[i]);
    }
}

__global__ void pack_x_kernel(const float4* __restrict__ X){
    int i = blockIdx.x * blockDim.x + threadIdx.x;  // over R_*D_/4
    float4 v = X[i];
    int m = i >> 8;          // D_/4 = 256 float4 per row
    int q = i & 255;
    int k0 = q << 2;
    int mb = m >> 7, msub = (m >> 4) & 7, r16 = m & 15;
    int rowbit = r16 >> 3, gr = r16 & 7;
    int kt = k0 >> 3, c4 = (k0 >> 2) & 1;
    size_t base = ((size_t)(mb*128 + kt))*1024 + msub*128 + gr*16 + ((c4<<1)|rowbit);
    g_Xa[base + 0 ] = tf32r(v.x);
    g_Xa[base + 4 ] = tf32r(v.y);
    g_Xa[base + 8 ] = tf32r(v.z);
    g_Xa[base + 12] = tf32r(v.w);
}

__global__ void zero_state_kernel(){
    int i = blockIdx.x * blockDim.x + threadIdx.x;
    if (i < B_*H_*8*64) g_Kv[i] = 0.f;
    if (i < B_*H_*8)    g_Ksum[i] = 0.f;
}

// ---------------- tf32 GEMM on packed operands -------------------------------
// BM=128, BN=128, BK=16, 3 stages, 128 threads (4 warps 2x2, warp tile 64x64).
// A, B already in fragment order -> LDS.128 (A) and LDS.64 (B), conflict-free.
// If expn!=0, tile column-block 0 (cols 0..127 = K region) gets exp()*mask.
__global__ __launch_bounds__(128)
void gemm_pk_kernel(const float* __restrict__ A, const float* __restrict__ Bp,
                    float* __restrict__ C, int N,
                    const float* __restrict__ mask, int expn){
    __shared__ float As[3*2048];   // 3 stages x 2 ktiles x 1024 floats (24 KB)
    __shared__ float Bs[3*2048];   // 24 KB

    const int tid  = threadIdx.x;
    const int w    = tid >> 5;
    const int lane = tid & 31;
    const int nb   = blockIdx.x;
    const int mb   = blockIdx.y;

    const float* Abase = A  + (size_t)mb * 131072;   // 128 ktiles * 1024
    const float* Bbase = Bp + (size_t)nb * 131072;

    const int wmsub = (w >> 1) * 4;   // A sub-tile base (of 8)
    const int wnsub = (w & 1) * 8;    // B sub-tile base (of 16)

    float c[4][8][4];
    #pragma unroll
    for (int a = 0; a < 4; a++)
        #pragma unroll
        for (int b = 0; b < 8; b++)
            #pragma unroll
            for (int e = 0; e < 4; e++) c[a][b][e] = 0.f;

    // stage copy: 2 contiguous ktiles (8 KB) each from A and B
    #define COPY_STAGE(buf, it) {                                            \
        const float* sa = Abase + (it)*2048;                                 \
        const float* sb = Bbase + (it)*2048;                                 \
        float* da = &As[(buf)*2048];                                         \
        float* db = &Bs[(buf)*2048];                                         \
        _Pragma("unroll")                                                    \
        for (int p = 0; p < 4; p++){                                         \
            cp16(da + p*512 + tid*4, sa + p*512 + tid*4);                    \
            cp16(db + p*512 + tid*4, sb + p*512 + tid*4);                    \
        }                                                                    \
    }

    COPY_STAGE(0, 0);
    asm volatile("cp.async.commit_group;" ::: "memory");
    COPY_STAGE(1, 1);
    asm volatile("cp.async.commit_group;" ::: "memory");

    int buf = 0;
    for (int it = 0; it < 64; ++it){
        asm volatile("cp.async.wait_group 1;" ::: "memory");
        __syncthreads();

        #pragma unroll
        for (int ktl = 0; ktl < 2; ++ktl){
            const float* as = &As[buf*2048 + ktl*1024 + wmsub*128 + lane*4];
            const float* bs = &Bs[buf*2048 + ktl*1024 + wnsub*64  + lane*2];
            float4 af[4]; float2 bf[8];
            #pragma unroll
            for (int mi = 0; mi < 4; ++mi)
                af[mi] = *reinterpret_cast<const float4*>(as + mi*128);
            #pragma unroll
            for (int ni = 0; ni < 8; ++ni)
                bf[ni] = *reinterpret_cast<const float2*>(bs + ni*64);
            #pragma unroll
            for (int mi = 0; mi < 4; ++mi)
                #pragma unroll
                for (int ni = 0; ni < 8; ++ni)
                    mma8(c[mi][ni],
                         __float_as_uint(af[mi].x), __float_as_uint(af[mi].y),
                         __float_as_uint(af[mi].z), __float_as_uint(af[mi].w),
                         __float_as_uint(bf[ni].x), __float_as_uint(bf[ni].y));
        }

        if (it + 2 < 64){
            int nbuf = buf + 2; if (nbuf >= 3) nbuf -= 3;
            COPY_STAGE(nbuf, it + 2);
        }
        asm volatile("cp.async.commit_group;" ::: "memory");
        buf = (buf + 1 == 3) ? 0 : buf + 1;
    }
    #undef COPY_STAGE

    // epilogue
    const int gr = lane >> 2, gc = lane & 3;
    const int wm = (w >> 1) * 64, wn = (w & 1) * 64;
    const bool doexp = (expn != 0) && (nb == 0);
    #pragma unroll
    for (int mi = 0; mi < 4; ++mi){
        int r0 = mb*128 + wm + mi*16 + gr;
        float m0 = 0.f, m1 = 0.f;
        if (doexp){ m0 = __ldg(mask + r0); m1 = __ldg(mask + r0 + 8); }
        #pragma unroll
        for (int ni = 0; ni < 8; ++ni){
            int c0 = nb*128 + wn + ni*8 + gc*2;
            float v0 = c[mi][ni][0], v1 = c[mi][ni][1];
            float v2 = c[mi][ni][2], v3 = c[mi][ni][3];
            if (doexp){
                v0 = __expf(v0)*m0; v1 = __expf(v1)*m0;
                v2 = __expf(v2)*m1; v3 = __expf(v3)*m1;
            }
            *reinterpret_cast<float2*>(&C[(size_t)r0*N + c0])     = make_float2(v0, v1);
            *reinterpret_cast<float2*>(&C[(size_t)(r0+8)*N + c0]) = make_float2(v2, v3);
        }
    }
}

// ---------------- Kv[b,h,l,d] = sum_t E[t,l] * (V[t,d]*m); Ksum = sum_t E ----
__global__ __launch_bounds__(256)
void kv_accum_kernel(const float* __restrict__ mask){
    int bh = blockIdx.x >> 4;
    int tc = blockIdx.x & 15;
    int b  = bh >> 4, h = bh & 15;
    int tid = threadIdx.x;
    int d  = tid & 63;
    int ls = tid >> 6;
    int l0 = ls*2, l1 = ls*2 + 1;

    __shared__ float Vs[16][64];
    __shared__ float Es[16][8];

    float acc0 = 0.f, acc1 = 0.f, ks0 = 0.f, ks1 = 0.f;
    const int rowbase = b * T_;
    const int t0 = tc * (T_/16);

    for (int it = 0; it < (T_/16)/16; ++it){
        int tb = t0 + it*16;
        #pragma unroll
        for (int q = 0; q < 4; ++q){
            int vi = q*256 + tid;
            int tt = vi >> 6, dd = vi & 63;
            int row = rowbase + tb + tt;
            Vs[tt][dd] = g_KQV[(size_t)row*NKQV + 256 + h*64 + dd] * mask[row];
        }
        if (tid < 128){
            int tt = tid >> 3, l = tid & 7;
            Es[tt][l] = g_KQV[(size_t)(rowbase + tb + tt)*NKQV + h*8 + l];
        }
        __syncthreads();
        #pragma unroll
        for (int tt = 0; tt < 16; ++tt){
            float v = Vs[tt][d];
            float e0 = Es[tt][l0], e1 = Es[tt][l1];
            acc0 += e0 * v;
            acc1 += e1 * v;
            if (d == 0){ ks0 += e0; ks1 += e1; }
        }
        __syncthreads();
    }
    atomicAdd(&g_Kv[(bh*8 + l0)*64 + d], acc0);
    atomicAdd(&g_Kv[(bh*8 + l1)*64 + d], acc1);
    if (d == 0){
        atomicAdd(&g_Ksum[bh*8 + l0], ks0);
        atomicAdd(&g_Ksum[bh*8 + l1], ks1);
    }
}

// ---------------- y = softmax(Q) @ (Kv/Ksum), packed + tf32-rounded ----------
__global__ __launch_bounds__(256)
void y_kernel(){
    int rb = blockIdx.x * 16;
    int b  = rb >> 13;
    int tid = threadIdx.x;

    __shared__ float Kvn[H_*8*64];
    __shared__ float Qs[16][128];

    for (int i = tid; i < H_*8*64; i += 256)
        Kvn[i] = g_Kv[b*(H_*8*64) + i] / g_Ksum[b*(H_*8) + (i >> 6)];

    {
        int rl = tid >> 4, h = tid & 15;
        const float* q = &g_KQV[(size_t)(rb + rl)*NKQV + 128 + h*8];
        float v[8]; float mx = -1e30f;
        #pragma unroll
        for (int j = 0; j < 8; ++j){ v[j] = q[j]; mx = fmaxf(mx, v[j]); }
        float s = 0.f;
        #pragma unroll
        for (int j = 0; j < 8; ++j){ v[j] = __expf(v[j] - mx); s += v[j]; }
        float inv = 1.f / s;
        #pragma unroll
        for (int j = 0; j < 8; ++j) Qs[rl][h*8 + j] = v[j] * inv;
    }
    __syncthreads();

    #pragma unroll
    for (int cq = 0; cq < 4; ++cq){
        int col = cq*256 + tid;
        int h = col >> 6, d = col & 63;
        int kt = col >> 3, kk = col & 7, gc = kk & 3, c4 = kk >> 2;
        float kv[8];
        #pragma unroll
        for (int l = 0; l < 8; ++l) kv[l] = Kvn[(h*8 + l)*64 + d];
        #pragma unroll
        for (int r = 0; r < 16; ++r){
            float y = 0.f;
            #pragma unroll
            for (int l = 0; l < 8; ++l) y += Qs[r][h*8 + l] * kv[l];
            int m = rb + r;
            int mb = m >> 7, msub = (m >> 4) & 7, r16 = m & 15;
            int rowbit = r16 >> 3, gr = r16 & 7;
            g_ya[((size_t)(mb*128 + kt))*1024 + msub*128 + (gr*4 + gc)*4
                 + ((c4<<1)|rowbit)] = tf32r(y);
        }
    }
}

// ---------------- launch -----------------------------------------------------
extern "C" void kernel_launch(void* const* d_in, const int* in_sizes, int n_in,
                              void* d_out, int out_size){
    const float* X    = (const float*)d_in[0];
    const float* mask = (const float*)d_in[1];
    const float* Wk   = (const float*)d_in[2];
    const float* Wq   = (const float*)d_in[3];
    const float* Wv   = (const float*)d_in[4];
    const float* Po   = (const float*)d_in[5];
    float* out = (float*)d_out;

    void *pXa, *pKQV, *pWcat, *pPop, *pYa;
    cudaGetSymbolAddress(&pXa,   g_Xa);
    cudaGetSymbolAddress(&pKQV,  g_KQV);
    cudaGetSymbolAddress(&pWcat, g_Wcat);
    cudaGetSymbolAddress(&pPop,  g_Pop);
    cudaGetSymbolAddress(&pYa,   g_ya);

    prep_weights_kernel<<<5120, 256>>>(Wk, Wq, Wv, Po);
    pack_x_kernel<<<(R_*D_/4)/256, 256>>>((const float4*)X);
    zero_state_kernel<<<(B_*H_*8*64 + 255)/256, 256>>>();

    dim3 g1(NKQV/128, R_/128);   // (10, 256)
    gemm_pk_kernel<<<g1, 128>>>((const float*)pXa, (const float*)pWcat,
                                (float*)pKQV, NKQV, mask, 1);

    kv_accum_kernel<<<B_*H_*16, 256>>>(mask);
    y_kernel<<<R_/16, 256>>>();

    dim3 g2(D_/128, R_/128);     // (8, 256)
    gemm_pk_kernel<<<g2, 128>>>((const float*)pYa, (const float*)pPop,
                                out, D_, (const float*)nullptr, 0);
}

// round 5
// speedup vs baseline: 2.2237x; 1.6250x over previous
#include <cuda_runtime.h>
#include <cuda_fp16.h>
#include <cstdint>

// Problem constants (fixed shapes)
#define B_  4
#define T_  8192
#define D_  1024
#define L_  128
#define H_  16
#define R_  (B_*T_)      // 32768 rows
#define NKQV 1280        // K(128) | Q(128) | V(1024)

// ---------------- scratch (device globals; allocation-free rule) -------------
// A operands packed in m16n8k16 fragment order:
//   b32 index = ((mb*64 + kt)*8 + msub)*128 + lane*4 + (hi8*2 + k8)
//   (uint4 per lane = regs a0,a2,a1,a3)
// B operands:
//   b32 index = ((nb*64 + kt)*16 + nsub)*64 + lane*2 + k8
__device__ __half g_Xpk[(size_t)R_*D_];      // A for GEMM1 (64 MB)
__device__ __half g_Ypk[(size_t)R_*D_];      // A for GEMM2 (64 MB)
__device__ __half g_Wpk[(size_t)D_*NKQV];    // B for GEMM1 (2.5 MB)
__device__ __half g_Ppk[(size_t)D_*D_];      // B for GEMM2 (2 MB)
__device__ float g_KQV[(size_t)R_*NKQV];     // GEMM1 out (160 MB)
__device__ float g_Kv  [B_*H_*8*64];
__device__ float g_Ksum[B_*H_*8];

// ---------------- helpers ----------------------------------------------------
__device__ __forceinline__ uint32_t f2h2(float a, float b){
    unsigned short lo = __half_as_ushort(__float2half_rn(a));
    unsigned short hi = __half_as_ushort(__float2half_rn(b));
    return (uint32_t)lo | ((uint32_t)hi << 16);
}

__device__ __forceinline__ void cp16(void* dst, const void* src){
    uint32_t d = (uint32_t)__cvta_generic_to_shared(dst);
    asm volatile("cp.async.cg.shared.global [%0], [%1], 16;" :: "r"(d), "l"(src));
}

__device__ __forceinline__ void mma16(float* c,
    uint32_t a0, uint32_t a1, uint32_t a2, uint32_t a3,
    uint32_t b0, uint32_t b1){
    asm volatile("mma.sync.aligned.m16n8k16.row.col.f32.f16.f16.f32 "
                 "{%0,%1,%2,%3}, {%4,%5,%6,%7}, {%8,%9}, {%0,%1,%2,%3};"
                 : "+f"(c[0]), "+f"(c[1]), "+f"(c[2]), "+f"(c[3])
                 : "r"(a0), "r"(a1), "r"(a2), "r"(a3), "r"(b0), "r"(b1));
}

// ---------------- prologue: pack X into A-fragment order ---------------------
__global__ void pack_x_kernel(const float* __restrict__ X){
    int i = blockIdx.x * blockDim.x + threadIdx.x;   // R_*D_/4 threads
    int t6    = i & 63;
    int group = i >> 6;            // (mb*64+kt)*8 + msub
    int gr  = t6 >> 3;
    int gc  = (t6 >> 1) & 3;
    int hi8 = t6 & 1;
    int msub = group & 7;
    int kt   = (group >> 3) & 63;
    int mb   = group >> 9;
    int m  = mb*128 + msub*16 + hi8*8 + gr;
    int k0 = kt*16 + gc*2;
    const float* xr = X + (size_t)m * D_ + k0;
    float2 v0 = *(const float2*)xr;
    float2 v1 = *(const float2*)(xr + 8);
    uint32_t h0 = f2h2(v0.x, v0.y);
    uint32_t h1 = f2h2(v1.x, v1.y);
    uint32_t* out = (uint32_t*)g_Xpk;
    size_t base = (size_t)group*128 + (gr*4 + gc)*4 + hi8*2;
    *(uint2*)(out + base) = make_uint2(h0, h1);
}

// ---------------- prologue: pack weights into B-fragment order ---------------
__global__ void prep_w_kernel(const float* __restrict__ Wk,
                              const float* __restrict__ Wq,
                              const float* __restrict__ Wv,
                              const float* __restrict__ Po){
    int i = blockIdx.x * blockDim.x + threadIdx.x;
    const int NW = 64 * NKQV;            // Wcat tasks: (kt, n)
    const int NP = 64 * D_;              // Po tasks
    if (i < NW){
        int n  = i % NKQV;
        int kt = i / NKQV;
        float f[16];
        #pragma unroll
        for (int j = 0; j < 16; ++j){
            int k = kt*16 + j;
            f[j] = (n < 128) ? Wk[k*L_ + n]
                 : (n < 256) ? Wq[k*L_ + (n-128)]
                             : Wv[k*D_ + (n-256)];
        }
        uint32_t arr[8];
        #pragma unroll
        for (int o = 0; o < 8; ++o){
            int gc = o >> 1, k8 = o & 1;
            int j = k8*8 + gc*2;
            arr[o] = f2h2(f[j], f[j+1]);
        }
        int nb = n >> 7, nl = n & 127, nsub = nl >> 3, gr = nl & 7;
        uint32_t* out = (uint32_t*)g_Wpk;
        size_t base = ((size_t)(nb*64 + kt)*16 + nsub)*64 + gr*8;
        *(uint4*)(out + base)     = make_uint4(arr[0], arr[1], arr[2], arr[3]);
        *(uint4*)(out + base + 4) = make_uint4(arr[4], arr[5], arr[6], arr[7]);
    } else if (i < NW + NP){
        int idx = i - NW;
        int n  = idx & 1023;
        int kt = idx >> 10;
        float f[16];
        #pragma unroll
        for (int j = 0; j < 16; ++j) f[j] = Po[(kt*16 + j)*D_ + n];
        uint32_t arr[8];
        #pragma unroll
        for (int o = 0; o < 8; ++o){
            int gc = o >> 1, k8 = o & 1;
            int j = k8*8 + gc*2;
            arr[o] = f2h2(f[j], f[j+1]);
        }
        int nb = n >> 7, nl = n & 127, nsub = nl >> 3, gr = nl & 7;
        uint32_t* out = (uint32_t*)g_Ppk;
        size_t base = ((size_t)(nb*64 + kt)*16 + nsub)*64 + gr*8;
        *(uint4*)(out + base)     = make_uint4(arr[0], arr[1], arr[2], arr[3]);
        *(uint4*)(out + base + 4) = make_uint4(arr[4], arr[5], arr[6], arr[7]);
    }
}

__global__ void zero_state_kernel(){
    int i = blockIdx.x * blockDim.x + threadIdx.x;
    if (i < B_*H_*8*64) g_Kv[i] = 0.f;
    if (i < B_*H_*8)    g_Ksum[i] = 0.f;
}

// ---------------- fp16 GEMM on packed fragment-order operands ----------------
// BM=128, BN=128, BK=32 (2 k16-tiles/stage), 3 stages, 128 threads
// (4 warps 2x2, warp tile 64x64). If expn!=0, global cols <128 get exp()*mask.
__global__ __launch_bounds__(128)
void gemm_fp16_kernel(const uint4* __restrict__ Apk, const uint4* __restrict__ Bpk,
                      float* __restrict__ C, int Nld,
                      const float* __restrict__ mask, int expn){
    __shared__ uint4 As[3*512];   // 3 stages x 2 ktiles x 256 uint4 (24 KB)
    __shared__ uint4 Bs[3*512];   // 24 KB

    const int tid  = threadIdx.x;
    const int w    = tid >> 5;
    const int lane = tid & 31;
    const int nb   = blockIdx.x;
    const int mb   = blockIdx.y;

    const uint4* Abase = Apk + (size_t)mb * (64*256);
    const uint4* Bbase = Bpk + (size_t)nb * (64*256);

    const int wmsub = (w >> 1) * 4;   // of 8 m-subtiles
    const int wnsub = (w & 1) * 8;    // of 16 n-subtiles

    float c[4][8][4];
    #pragma unroll
    for (int a = 0; a < 4; a++)
        #pragma unroll
        for (int b = 0; b < 8; b++)
            #pragma unroll
            for (int e = 0; e < 4; e++) c[a][b][e] = 0.f;

    // stage = 2 consecutive ktiles: 512 uint4 from each of A and B
    #define COPY_STAGE(buf, it) {                                            \
        const uint4* sa = Abase + (size_t)(it)*512;                          \
        const uint4* sb = Bbase + (size_t)(it)*512;                          \
        uint4* da = &As[(buf)*512];                                          \
        uint4* db = &Bs[(buf)*512];                                          \
        _Pragma("unroll")                                                    \
        for (int p = 0; p < 4; p++){                                         \
            cp16(da + p*128 + tid, sa + p*128 + tid);                        \
            cp16(db + p*128 + tid, sb + p*128 + tid);                        \
        }                                                                    \
    }

    COPY_STAGE(0, 0);
    asm volatile("cp.async.commit_group;" ::: "memory");
    COPY_STAGE(1, 1);
    asm volatile("cp.async.commit_group;" ::: "memory");

    int buf = 0;
    for (int it = 0; it < 32; ++it){
        asm volatile("cp.async.wait_group 1;" ::: "memory");
        __syncthreads();

        #pragma unroll
        for (int ktl = 0; ktl < 2; ++ktl){
            const uint4* as = &As[buf*512 + ktl*256];
            const uint4* bs = &Bs[buf*512 + ktl*256];
            uint4 af[4]; uint2 bf[8];
            #pragma unroll
            for (int mi = 0; mi < 4; ++mi)
                af[mi] = as[(wmsub + mi)*32 + lane];
            #pragma unroll
            for (int ni = 0; ni < 8; ++ni)
                bf[ni] = *(const uint2*)((const uint32_t*)bs
                                         + (wnsub + ni)*64 + lane*2);
            #pragma unroll
            for (int mi = 0; mi < 4; ++mi)
                #pragma unroll
                for (int ni = 0; ni < 8; ++ni)
                    // packed order (a0,a2,a1,a3) -> args a0,a1,a2,a3
                    mma16(c[mi][ni], af[mi].x, af[mi].z, af[mi].y, af[mi].w,
                          bf[ni].x, bf[ni].y);
        }

        if (it + 2 < 32){
            int nbuf = buf + 2; if (nbuf >= 3) nbuf -= 3;
            COPY_STAGE(nbuf, it + 2);
        }
        asm volatile("cp.async.commit_group;" ::: "memory");
        buf = (buf + 1 == 3) ? 0 : buf + 1;
    }
    #undef COPY_STAGE

    // epilogue
    const int gr = lane >> 2, gc = lane & 3;
    const int wm = (w >> 1) * 64, wn = (w & 1) * 64;
    const bool doexp = (expn != 0) && (nb == 0);
    #pragma unroll
    for (int mi = 0; mi < 4; ++mi){
        int r0 = mb*128 + wm + mi*16 + gr;
        float m0 = 0.f, m1 = 0.f;
        if (doexp){ m0 = __ldg(mask + r0); m1 = __ldg(mask + r0 + 8); }
        #pragma unroll
        for (int ni = 0; ni < 8; ++ni){
            int c0 = nb*128 + wn + ni*8 + gc*2;
            float v0 = c[mi][ni][0], v1 = c[mi][ni][1];
            float v2 = c[mi][ni][2], v3 = c[mi][ni][3];
            if (doexp){
                v0 = __expf(v0)*m0; v1 = __expf(v1)*m0;
                v2 = __expf(v2)*m1; v3 = __expf(v3)*m1;
            }
            *reinterpret_cast<float2*>(&C[(size_t)r0*Nld + c0])     = make_float2(v0, v1);
            *reinterpret_cast<float2*>(&C[(size_t)(r0+8)*Nld + c0]) = make_float2(v2, v3);
        }
    }
}

// ---------------- Kv[b,h,l,d] = sum_t E[t,l]*(V[t,d]*m); Ksum = sum_t E ------
__global__ __launch_bounds__(256)
void kv_accum_kernel(const float* __restrict__ mask){
    int bh = blockIdx.x >> 4;
    int tc = blockIdx.x & 15;
    int b  = bh >> 4, h = bh & 15;
    int tid = threadIdx.x;
    int d  = tid & 63;
    int ls = tid >> 6;
    int l0 = ls*2, l1 = ls*2 + 1;

    __shared__ float Vs[16][64];
    __shared__ float Es[16][8];

    float acc0 = 0.f, acc1 = 0.f, ks0 = 0.f, ks1 = 0.f;
    const int rowbase = b * T_;
    const int t0 = tc * (T_/16);

    for (int it = 0; it < (T_/16)/16; ++it){
        int tb = t0 + it*16;
        #pragma unroll
        for (int q = 0; q < 4; ++q){
            int vi = q*256 + tid;
            int tt = vi >> 6, dd = vi & 63;
            int row = rowbase + tb + tt;
            Vs[tt][dd] = g_KQV[(size_t)row*NKQV + 256 + h*64 + dd] * mask[row];
        }
        if (tid < 128){
            int tt = tid >> 3, l = tid & 7;
            Es[tt][l] = g_KQV[(size_t)(rowbase + tb + tt)*NKQV + h*8 + l];
        }
        __syncthreads();
        #pragma unroll
        for (int tt = 0; tt < 16; ++tt){
            float v = Vs[tt][d];
            float e0 = Es[tt][l0], e1 = Es[tt][l1];
            acc0 += e0 * v;
            acc1 += e1 * v;
            if (d == 0){ ks0 += e0; ks1 += e1; }
        }
        __syncthreads();
    }
    atomicAdd(&g_Kv[(bh*8 + l0)*64 + d], acc0);
    atomicAdd(&g_Kv[(bh*8 + l1)*64 + d], acc1);
    if (d == 0){
        atomicAdd(&g_Ksum[bh*8 + l0], ks0);
        atomicAdd(&g_Ksum[bh*8 + l1], ks1);
    }
}

// ---------------- y = softmax(Q) @ (Kv/Ksum), packed fp16 A layout -----------
__global__ __launch_bounds__(256)
void y_kernel(){
    int rb = blockIdx.x * 16;
    int b  = rb >> 13;
    int tid = threadIdx.x;

    __shared__ float Kvn[H_*8*64];
    __shared__ float Qs[16][128];

    for (int i = tid; i < H_*8*64; i += 256)
        Kvn[i] = g_Kv[b*(H_*8*64) + i] / g_Ksum[b*(H_*8) + (i >> 6)];

    {
        int rl = tid >> 4, h = tid & 15;
        const float* q = &g_KQV[(size_t)(rb + rl)*NKQV + 128 + h*8];
        float v[8]; float mx = -1e30f;
        #pragma unroll
        for (int j = 0; j < 8; ++j){ v[j] = q[j]; mx = fmaxf(mx, v[j]); }
        float s = 0.f;
        #pragma unroll
        for (int j = 0; j < 8; ++j){ v[j] = __expf(v[j] - mx); s += v[j]; }
        float inv = 1.f / s;
        #pragma unroll
        for (int j = 0; j < 8; ++j) Qs[rl][h*8 + j] = v[j] * inv;
    }
    __syncthreads();

    uint32_t* out = (uint32_t*)g_Ypk;
    #pragma unroll
    for (int cq = 0; cq < 2; ++cq){
        int colp = cq*256 + tid;      // pair of columns (2*colp, 2*colp+1)
        int c0 = colp*2;
        int h = c0 >> 6, d0 = c0 & 63;
        float kva[8], kvb[8];
        #pragma unroll
        for (int l = 0; l < 8; ++l){
            kva[l] = Kvn[(h*8 + l)*64 + d0];
            kvb[l] = Kvn[(h*8 + l)*64 + d0 + 1];
        }
        int kt = c0 >> 4, kk = c0 & 15;
        int gc = (kk >> 1) & 3, k8 = kk >> 3;
        #pragma unroll
        for (int r = 0; r < 16; ++r){
            float y0 = 0.f, y1 = 0.f;
            #pragma unroll
            for (int l = 0; l < 8; ++l){
                float qv = Qs[r][h*8 + l];
                y0 += qv * kva[l];
                y1 += qv * kvb[l];
            }
            int m = rb + r;
            int mb = m >> 7, msub = (m >> 4) & 7, r16 = m & 15;
            int hi8 = r16 >> 3, gr = r16 & 7;
            size_t off = ((size_t)(mb*64 + kt)*8 + msub)*128
                       + (gr*4 + gc)*4 + hi8*2 + k8;
            out[off] = f2h2(y0, y1);
        }
    }
}

// ---------------- launch -----------------------------------------------------
extern "C" void kernel_launch(void* const* d_in, const int* in_sizes, int n_in,
                              void* d_out, int out_size){
    const float* X    = (const float*)d_in[0];
    const float* mask = (const float*)d_in[1];
    const float* Wk   = (const float*)d_in[2];
    const float* Wq   = (const float*)d_in[3];
    const float* Wv   = (const float*)d_in[4];
    const float* Po   = (const float*)d_in[5];
    float* out = (float*)d_out;

    void *pXpk, *pYpk, *pWpk, *pPpk, *pKQV;
    cudaGetSymbolAddress(&pXpk, g_Xpk);
    cudaGetSymbolAddress(&pYpk, g_Ypk);
    cudaGetSymbolAddress(&pWpk, g_Wpk);
    cudaGetSymbolAddress(&pPpk, g_Ppk);
    cudaGetSymbolAddress(&pKQV, g_KQV);

    prep_w_kernel<<<(64*NKQV + 64*D_ + 255)/256, 256>>>(Wk, Wq, Wv, Po);
    pack_x_kernel<<<(R_*D_/4)/256, 256>>>(X);
    zero_state_kernel<<<(B_*H_*8*64 + 255)/256, 256>>>();

    dim3 g1(NKQV/128, R_/128);   // (10, 256)
    gemm_fp16_kernel<<<g1, 128>>>((const uint4*)pXpk, (const uint4*)pWpk,
                                  (float*)pKQV, NKQV, mask, 1);

    kv_accum_kernel<<<B_*H_*16, 256>>>(mask);
    y_kernel<<<R_/16, 256>>>();

    dim3 g2(D_/128, R_/128);     // (8, 256)
    gemm_fp16_kernel<<<g2, 128>>>((const uint4*)pYpk, (const uint4*)pPpk,
                                  out, D_, (const float*)nullptr, 0);
}

// round 6
// speedup vs baseline: 3.1771x; 1.4288x over previous
#include <cuda_runtime.h>
#include <cuda_fp16.h>
#include <cstdint>

// Problem constants (fixed shapes)
#define B_  4
#define T_  8192
#define D_  1024
#define L_  128
#define H_  16
#define R_  (B_*T_)      // 32768 rows
#define NKQV 1280        // K(128) | Q(128) | V(1024)

// ---------------- scratch (device globals; allocation-free rule) -------------
// A operands packed in m16n8k16 fragment order (aktiles = K/16):
//   b32 index = ((mb*aktiles + kt)*8 + msub)*128 + (gr*4+gc)*4 + hi8*2 + k8
// B operands:
//   b32 index = ((nb*aktiles + kt)*16 + nsub)*64 + (gr*4+gc)*2 + k8
__device__ __half g_Xpk[(size_t)R_*D_];      // A for GEMM1 (64 MB)
__device__ __half g_Wpk[(size_t)D_*NKQV];    // B for GEMM1 (2.5 MB)
__device__ __half g_Qs [(size_t)R_*L_];      // A for GEMM2: softmax(Q) (8 MB)
__device__ __half g_Z  [(size_t)B_*L_*D_];   // B for GEMM2 (1 MB, per-batch)
__device__ float g_KQV[(size_t)R_*NKQV];     // GEMM1 out (160 MB)
__device__ float g_Kv  [B_*H_*8*64];
__device__ float g_Ksum[B_*H_*8];

// ---------------- helpers ----------------------------------------------------
__device__ __forceinline__ uint32_t f2h2(float a, float b){
    unsigned short lo = __half_as_ushort(__float2half_rn(a));
    unsigned short hi = __half_as_ushort(__float2half_rn(b));
    return (uint32_t)lo | ((uint32_t)hi << 16);
}

__device__ __forceinline__ void cp16(void* dst, const void* src){
    uint32_t d = (uint32_t)__cvta_generic_to_shared(dst);
    asm volatile("cp.async.cg.shared.global [%0], [%1], 16;" :: "r"(d), "l"(src));
}

__device__ __forceinline__ void mma16(float* c,
    uint32_t a0, uint32_t a1, uint32_t a2, uint32_t a3,
    uint32_t b0, uint32_t b1){
    asm volatile("mma.sync.aligned.m16n8k16.row.col.f32.f16.f16.f32 "
                 "{%0,%1,%2,%3}, {%4,%5,%6,%7}, {%8,%9}, {%0,%1,%2,%3};"
                 : "+f"(c[0]), "+f"(c[1]), "+f"(c[2]), "+f"(c[3])
                 : "r"(a0), "r"(a1), "r"(a2), "r"(a3), "r"(b0), "r"(b1));
}

// ---------------- prologue: pack X into A-fragment order ---------------------
__global__ void pack_x_kernel(const float* __restrict__ X){
    int i = blockIdx.x * blockDim.x + threadIdx.x;   // R_*D_/4 threads
    int t6    = i & 63;
    int group = i >> 6;            // (mb*64+kt)*8 + msub
    int gr  = t6 >> 3;
    int gc  = (t6 >> 1) & 3;
    int hi8 = t6 & 1;
    int msub = group & 7;
    int kt   = (group >> 3) & 63;
    int mb   = group >> 9;
    int m  = mb*128 + msub*16 + hi8*8 + gr;
    int k0 = kt*16 + gc*2;
    const float* xr = X + (size_t)m * D_ + k0;
    float2 v0 = *(const float2*)xr;
    float2 v1 = *(const float2*)(xr + 8);
    uint32_t h0 = f2h2(v0.x, v0.y);
    uint32_t h1 = f2h2(v1.x, v1.y);
    uint32_t* out = (uint32_t*)g_Xpk;
    size_t base = (size_t)group*128 + (gr*4 + gc)*4 + hi8*2;
    *(uint2*)(out + base) = make_uint2(h0, h1);
}

// ---------------- prologue: pack weights into B-fragment order ---------------
__global__ void prep_w_kernel(const float* __restrict__ Wk,
                              const float* __restrict__ Wq,
                              const float* __restrict__ Wv){
    int i = blockIdx.x * blockDim.x + threadIdx.x;
    const int NW = 64 * NKQV;            // (kt, n) tasks
    if (i >= NW) return;
    int n  = i % NKQV;
    int kt = i / NKQV;
    float f[16];
    #pragma unroll
    for (int j = 0; j < 16; ++j){
        int k = kt*16 + j;
        f[j] = (n < 128) ? Wk[k*L_ + n]
             : (n < 256) ? Wq[k*L_ + (n-128)]
                         : Wv[k*D_ + (n-256)];
    }
    uint32_t arr[8];
    #pragma unroll
    for (int o = 0; o < 8; ++o){
        int gc = o >> 1, k8 = o & 1;
        int j = k8*8 + gc*2;
        arr[o] = f2h2(f[j], f[j+1]);
    }
    int nb = n >> 7, nl = n & 127, nsub = nl >> 3, gr = nl & 7;
    uint32_t* out = (uint32_t*)g_Wpk;
    size_t base = ((size_t)(nb*64 + kt)*16 + nsub)*64 + gr*8;
    *(uint4*)(out + base)     = make_uint4(arr[0], arr[1], arr[2], arr[3]);
    *(uint4*)(out + base + 4) = make_uint4(arr[4], arr[5], arr[6], arr[7]);
}

__global__ void zero_state_kernel(){
    int i = blockIdx.x * blockDim.x + threadIdx.x;
    if (i < B_*H_*8*64) g_Kv[i] = 0.f;
    if (i < B_*H_*8)    g_Ksum[i] = 0.f;
}

// ---------------- fp16 GEMM on packed fragment-order operands ----------------
// BM=128, BN=128, BK=32, 3 stages, 128 threads (4 warps 2x2, warp tile 64x64).
// aktiles = K/16 (runtime); B batch selected by mb>>6 via bb_u4 stride.
// If expn!=0, global cols <128 get exp()*mask.
__global__ __launch_bounds__(128)
void gemm_fp16_kernel(const uint4* __restrict__ Apk, const uint4* __restrict__ Bpk,
                      float* __restrict__ C, int Nld,
                      const float* __restrict__ mask, int expn,
                      int aktiles, long bb_u4){
    __shared__ uint4 As[3*512];   // 3 stages x 2 ktiles x 256 uint4 (24 KB)
    __shared__ uint4 Bs[3*512];   // 24 KB

    const int tid  = threadIdx.x;
    const int w    = tid >> 5;
    const int lane = tid & 31;
    const int nb   = blockIdx.x;
    const int mb   = blockIdx.y;

    const uint4* Abase = Apk + (size_t)mb * aktiles * 256;
    const uint4* Bbase = Bpk + (size_t)(mb >> 6) * bb_u4
                             + (size_t)nb * aktiles * 256;

    const int wmsub = (w >> 1) * 4;   // of 8 m-subtiles
    const int wnsub = (w & 1) * 8;    // of 16 n-subtiles
    const int niter = aktiles >> 1;

    float c[4][8][4];
    #pragma unroll
    for (int a = 0; a < 4; a++)
        #pragma unroll
        for (int b = 0; b < 8; b++)
            #pragma unroll
            for (int e = 0; e < 4; e++) c[a][b][e] = 0.f;

    #define COPY_STAGE(buf, it) {                                            \
        const uint4* sa = Abase + (size_t)(it)*512;                          \
        const uint4* sb = Bbase + (size_t)(it)*512;                          \
        uint4* da = &As[(buf)*512];                                          \
        uint4* db = &Bs[(buf)*512];                                          \
        _Pragma("unroll")                                                    \
        for (int p = 0; p < 4; p++){                                         \
            cp16(da + p*128 + tid, sa + p*128 + tid);                        \
            cp16(db + p*128 + tid, sb + p*128 + tid);                        \
        }                                                                    \
    }

    COPY_STAGE(0, 0);
    asm volatile("cp.async.commit_group;" ::: "memory");
    COPY_STAGE(1, 1);
    asm volatile("cp.async.commit_group;" ::: "memory");

    int buf = 0;
    for (int it = 0; it < niter; ++it){
        asm volatile("cp.async.wait_group 1;" ::: "memory");
        __syncthreads();

        #pragma unroll
        for (int ktl = 0; ktl < 2; ++ktl){
            const uint4* as = &As[buf*512 + ktl*256];
            const uint4* bs = &Bs[buf*512 + ktl*256];
            uint4 af[4]; uint2 bf[8];
            #pragma unroll
            for (int mi = 0; mi < 4; ++mi)
                af[mi] = as[(wmsub + mi)*32 + lane];
            #pragma unroll
            for (int ni = 0; ni < 8; ++ni)
                bf[ni] = *(const uint2*)((const uint32_t*)bs
                                         + (wnsub + ni)*64 + lane*2);
            #pragma unroll
            for (int mi = 0; mi < 4; ++mi)
                #pragma unroll
                for (int ni = 0; ni < 8; ++ni)
                    // packed order (a0,a2,a1,a3) -> args a0,a1,a2,a3
                    mma16(c[mi][ni], af[mi].x, af[mi].z, af[mi].y, af[mi].w,
                          bf[ni].x, bf[ni].y);
        }

        if (it + 2 < niter){
            int nbuf = buf + 2; if (nbuf >= 3) nbuf -= 3;
            COPY_STAGE(nbuf, it + 2);
        }
        asm volatile("cp.async.commit_group;" ::: "memory");
        buf = (buf + 1 == 3) ? 0 : buf + 1;
    }
    #undef COPY_STAGE

    // epilogue
    const int gr = lane >> 2, gc = lane & 3;
    const int wm = (w >> 1) * 64, wn = (w & 1) * 64;
    const bool doexp = (expn != 0) && (nb == 0);
    #pragma unroll
    for (int mi = 0; mi < 4; ++mi){
        int r0 = mb*128 + wm + mi*16 + gr;
        float m0 = 0.f, m1 = 0.f;
        if (doexp){ m0 = __ldg(mask + r0); m1 = __ldg(mask + r0 + 8); }
        #pragma unroll
        for (int ni = 0; ni < 8; ++ni){
            int c0 = nb*128 + wn + ni*8 + gc*2;
            float v0 = c[mi][ni][0], v1 = c[mi][ni][1];
            float v2 = c[mi][ni][2], v3 = c[mi][ni][3];
            if (doexp){
                v0 = __expf(v0)*m0; v1 = __expf(v1)*m0;
                v2 = __expf(v2)*m1; v3 = __expf(v3)*m1;
            }
            *reinterpret_cast<float2*>(&C[(size_t)r0*Nld + c0])     = make_float2(v0, v1);
            *reinterpret_cast<float2*>(&C[(size_t)(r0+8)*Nld + c0]) = make_float2(v2, v3);
        }
    }
}

// ---------------- Kv[b,h,l,d] = sum_t E[t,l]*(V[t,d]*m); Ksum = sum_t E ------
__global__ __launch_bounds__(256)
void kv_accum_kernel(const float* __restrict__ mask){
    int bh = blockIdx.x >> 4;
    int tc = blockIdx.x & 15;
    int b  = bh >> 4, h = bh & 15;
    int tid = threadIdx.x;
    int d  = tid & 63;
    int ls = tid >> 6;
    int l0 = ls*2, l1 = ls*2 + 1;

    __shared__ float Vs[16][64];
    __shared__ float Es[16][8];

    float acc0 = 0.f, acc1 = 0.f, ks0 = 0.f, ks1 = 0.f;
    const int rowbase = b * T_;
    const int t0 = tc * (T_/16);

    for (int it = 0; it < (T_/16)/16; ++it){
        int tb = t0 + it*16;
        #pragma unroll
        for (int q = 0; q < 4; ++q){
            int vi = q*256 + tid;
            int tt = vi >> 6, dd = vi & 63;
            int row = rowbase + tb + tt;
            Vs[tt][dd] = g_KQV[(size_t)row*NKQV + 256 + h*64 + dd] * mask[row];
        }
        if (tid < 128){
            int tt = tid >> 3, l = tid & 7;
            Es[tt][l] = g_KQV[(size_t)(rowbase + tb + tt)*NKQV + h*8 + l];
        }
        __syncthreads();
        #pragma unroll
        for (int tt = 0; tt < 16; ++tt){
            float v = Vs[tt][d];
            float e0 = Es[tt][l0], e1 = Es[tt][l1];
            acc0 += e0 * v;
            acc1 += e1 * v;
            if (d == 0){ ks0 += e0; ks1 += e1; }
        }
        __syncthreads();
    }
    atomicAdd(&g_Kv[(bh*8 + l0)*64 + d], acc0);
    atomicAdd(&g_Kv[(bh*8 + l1)*64 + d], acc1);
    if (d == 0){
        atomicAdd(&g_Ksum[bh*8 + l0], ks0);
        atomicAdd(&g_Ksum[bh*8 + l1], ks1);
    }
}

// ---------------- Qs = softmax(Q) per (row, head), packed as A-frag ----------
__global__ __launch_bounds__(256)
void qs_kernel(){
    int i = blockIdx.x * 256 + threadIdx.x;   // R_*16
    int row = i >> 4, h = i & 15;
    const float* q = &g_KQV[(size_t)row*NKQV + 128 + h*8];
    float v[8]; float mx = -1e30f;
    #pragma unroll
    for (int j = 0; j < 8; ++j){ v[j] = q[j]; mx = fmaxf(mx, v[j]); }
    float s = 0.f;
    #pragma unroll
    for (int j = 0; j < 8; ++j){ v[j] = __expf(v[j] - mx); s += v[j]; }
    float inv = 1.f / s;
    #pragma unroll
    for (int j = 0; j < 8; ++j) v[j] *= inv;

    int mb = row >> 7, msub = (row >> 4) & 7, r16 = row & 15;
    int hi8 = r16 >> 3, gr = r16 & 7;
    int kt = h >> 1, k8 = h & 1;
    uint32_t* out = (uint32_t*)g_Qs;
    size_t base = ((size_t)(mb*8 + kt)*8 + msub)*128 + gr*16 + hi8*2 + k8;
    #pragma unroll
    for (int j2 = 0; j2 < 4; ++j2)
        out[base + j2*4] = f2h2(v[2*j2], v[2*j2+1]);
}

// ---------------- Z[b,(h,l),n] = sum_d (Kv/Ksum)[b,h,l,d] * Po[h*64+d, n] ----
__global__ __launch_bounds__(256)
void z_kernel(const float* __restrict__ Po){
    int bid = blockIdx.x;           // b*64 + h*4 + nc
    int b = bid >> 6, h = (bid >> 2) & 15, nc = bid & 3;
    int tid = threadIdx.x;

    __shared__ float kvn[8][64];
    for (int j = tid; j < 512; j += 256){
        int l = j >> 6, d = j & 63;
        kvn[l][d] = g_Kv[((b*16 + h)*8 + l)*64 + d]
                  / g_Ksum[(b*16 + h)*8 + l];
    }
    __syncthreads();

    int n = nc*256 + tid;
    float acc[8];
    #pragma unroll
    for (int l = 0; l < 8; ++l) acc[l] = 0.f;
    for (int d = 0; d < 64; ++d){
        float po = __ldg(Po + (size_t)(h*64 + d)*1024 + n);
        #pragma unroll
        for (int l = 0; l < 8; ++l) acc[l] += kvn[l][d] * po;
    }

    int nb = n >> 7, nsub = (n & 127) >> 3, gr = n & 7;
    int kt = h >> 1, k8 = h & 1;
    uint32_t* out = (uint32_t*)g_Z;
    size_t base = (((size_t)(b*8 + nb)*8 + kt)*16 + nsub)*64 + gr*8 + k8;
    #pragma unroll
    for (int j2 = 0; j2 < 4; ++j2)
        out[base + j2*2] = f2h2(acc[2*j2], acc[2*j2+1]);
}

// ---------------- launch -----------------------------------------------------
extern "C" void kernel_launch(void* const* d_in, const int* in_sizes, int n_in,
                              void* d_out, int out_size){
    const float* X    = (const float*)d_in[0];
    const float* mask = (const float*)d_in[1];
    const float* Wk   = (const float*)d_in[2];
    const float* Wq   = (const float*)d_in[3];
    const float* Wv   = (const float*)d_in[4];
    const float* Po   = (const float*)d_in[5];
    float* out = (float*)d_out;

    void *pXpk, *pWpk, *pQs, *pZ, *pKQV;
    cudaGetSymbolAddress(&pXpk, g_Xpk);
    cudaGetSymbolAddress(&pWpk, g_Wpk);
    cudaGetSymbolAddress(&pQs,  g_Qs);
    cudaGetSymbolAddress(&pZ,   g_Z);
    cudaGetSymbolAddress(&pKQV, g_KQV);

    prep_w_kernel<<<(64*NKQV + 255)/256, 256>>>(Wk, Wq, Wv);
    pack_x_kernel<<<(R_*D_/4)/256, 256>>>(X);
    zero_state_kernel<<<(B_*H_*8*64 + 255)/256, 256>>>();

    dim3 g1(NKQV/128, R_/128);   // (10, 256)
    gemm_fp16_kernel<<<g1, 128>>>((const uint4*)pXpk, (const uint4*)pWpk,
                                  (float*)pKQV, NKQV, mask, 1, 64, 0);

    kv_accum_kernel<<<B_*H_*16, 256>>>(mask);
    qs_kernel<<<R_*16/256, 256>>>();
    z_kernel<<<B_*H_*4, 256>>>(Po);

    // GEMM2: out[32768,1024] = Qs[32768,128] @ Z_b[128,1024]
    // per-batch B stride = 8nb * 8kt * 256 u4 = 16384 u4
    dim3 g2(D_/128, R_/128);     // (8, 256)
    gemm_fp16_kernel<<<g2, 128>>>((const uint4*)pQs, (const uint4*)pZ,
                                  out, D_, (const float*)nullptr, 0, 8, 16384);
}

// round 7
// speedup vs baseline: 4.1606x; 1.3095x over previous
#include <cuda_runtime.h>
#include <cuda_fp16.h>
#include <cstdint>

// Problem constants (fixed shapes)
#define B_  4
#define T_  8192
#define D_  1024
#define L_  128
#define H_  16
#define R_  (B_*T_)      // 32768 rows

// ---------------- scratch (device globals; allocation-free rule) -------------
// A-frag layout (m16n8k16), element (m,k):
//   b32 = ((mb*aktiles + (k>>4))*8 + ((m>>4)&7))*128
//         + (m&7)*16 + ((k&7)>>1)*4 + ((m>>3)&1)*2 + ((k>>3)&1); half = k&1
// B-frag layout, element (k,n):
//   b32 = ((nb*aktiles + (k>>4))*16 + ((n&127)>>3))*64
//         + (n&7)*8 + ((k&7)>>1)*2 + ((k>>3)&1); half = k&1
__device__ __half g_Xpk[(size_t)R_*D_];     // A-frag X            (64 MB)
__device__ __half g_XT [(size_t)R_*D_];     // B-frag X (contraction=t) (64 MB)
__device__ __half g_Wpk[(size_t)D_*256];    // B-frag [Wk|Wq]      (0.5 MB)
__device__ __half g_ET [(size_t)R_*L_];     // A-frag Em^T per batch (8 MB)
__device__ __half g_Qs [(size_t)R_*L_];     // A-frag softmax(Q)   (8 MB)
__device__ __half g_Z  [(size_t)B_*L_*D_];  // B-frag Z            (1 MB)
__device__ float  g_G  [(size_t)B_*L_*D_];  // fp32 G = Em^T @ X   (2 MB)
__device__ float  g_Kv [B_*H_*8*64];        // normalized Kv
__device__ float  g_Ksum[B_*L_];

// ---------------- helpers ----------------------------------------------------
__device__ __forceinline__ uint32_t f2h2(float a, float b){
    unsigned short lo = __half_as_ushort(__float2half_rn(a));
    unsigned short hi = __half_as_ushort(__float2half_rn(b));
    return (uint32_t)lo | ((uint32_t)hi << 16);
}

__device__ __forceinline__ void cp16(void* dst, const void* src){
    uint32_t d = (uint32_t)__cvta_generic_to_shared(dst);
    asm volatile("cp.async.cg.shared.global [%0], [%1], 16;" :: "r"(d), "l"(src));
}

__device__ __forceinline__ void mma16(float* c,
    uint32_t a0, uint32_t a1, uint32_t a2, uint32_t a3,
    uint32_t b0, uint32_t b1){
    asm volatile("mma.sync.aligned.m16n8k16.row.col.f32.f16.f16.f32 "
                 "{%0,%1,%2,%3}, {%4,%5,%6,%7}, {%8,%9}, {%0,%1,%2,%3};"
                 : "+f"(c[0]), "+f"(c[1]), "+f"(c[2]), "+f"(c[3])
                 : "r"(a0), "r"(a1), "r"(a2), "r"(a3), "r"(b0), "r"(b1));
}

// ---------------- combined pack: X -> A-frag and B-frag(t-contraction) -------
__global__ __launch_bounds__(256)
void pack_xc_kernel(const float* __restrict__ X){
    __shared__ float sm[16][129];
    const int blk  = blockIdx.x;           // 16384 = (T_total/16) * (1024/128)
    const int Dblk = blk & 7,  Tblk = blk >> 3;
    const int T0 = Tblk*16,  D0 = Dblk*128;
    const int tid = threadIdx.x;
    {
        int row = tid >> 4, c8 = (tid & 15) << 3;
        const float* src = X + (size_t)(T0 + row)*D_ + D0 + c8;
        float4 v0 = *(const float4*)src;
        float4 v1 = *(const float4*)(src + 4);
        sm[row][c8+0]=v0.x; sm[row][c8+1]=v0.y; sm[row][c8+2]=v0.z; sm[row][c8+3]=v0.w;
        sm[row][c8+4]=v1.x; sm[row][c8+5]=v1.y; sm[row][c8+6]=v1.z; sm[row][c8+7]=v1.w;
    }
    __syncthreads();

    // A-frag: m=t(16 rows), k=D(128)
    uint32_t* oA = (uint32_t*)g_Xpk;
    const int mb = T0 >> 7, msub = (T0 >> 4) & 7;
    #pragma unroll
    for (int q = 0; q < 4; ++q){
        int a = q*256 + tid;               // 0..1023
        int kt_l = a >> 7, r = a & 127;
        int gr = r >> 4, gc = (r >> 2) & 3, hi8 = (r >> 1) & 1, k8 = r & 1;
        int m = hi8*8 + gr;
        int k = kt_l*16 + k8*8 + gc*2;
        oA[(size_t)(mb*64 + (D0>>4) + kt_l)*1024 + msub*128 + r]
            = f2h2(sm[m][k], sm[m][k+1]);
    }

    // B-frag: k=t(16), n=D(128)  -> 1024 contiguous b32
    uint32_t* oB = (uint32_t*)g_XT;
    const int bb = T0 >> 13, ktT = (T0 & 8191) >> 4;
    size_t gB = (((size_t)(bb*8 + Dblk)*512 + ktT)*16)*64;
    #pragma unroll
    for (int q = 0; q < 4; ++q){
        int bx = q*256 + tid;              // 0..1023
        int nsub = bx >> 6, rr = bx & 63;
        int grD = rr >> 3, gcT = (rr >> 1) & 3, k8T = rr & 1;
        int Dl = nsub*8 + grD;
        int tl = k8T*8 + gcT*2;
        oB[gB + bx] = f2h2(sm[tl][Dl], sm[tl+1][Dl]);
    }
}

// ---------------- weights [Wk|Wq] -> B-frag ----------------------------------
__global__ void prep_w_kernel(const float* __restrict__ Wk,
                              const float* __restrict__ Wq){
    int i = blockIdx.x * blockDim.x + threadIdx.x;   // 64*256
    int n  = i & 255;
    int kt = i >> 8;
    float f[16];
    #pragma unroll
    for (int j = 0; j < 16; ++j){
        int k = kt*16 + j;
        f[j] = (n < 128) ? Wk[k*L_ + n] : Wq[k*L_ + (n-128)];
    }
    uint32_t arr[8];
    #pragma unroll
    for (int o = 0; o < 8; ++o){
        int gc = o >> 1, k8 = o & 1;
        int j = k8*8 + gc*2;
        arr[o] = f2h2(f[j], f[j+1]);
    }
    int nb = n >> 7, nl = n & 127, nsub = nl >> 3, gr = nl & 7;
    uint32_t* out = (uint32_t*)g_Wpk;
    size_t base = ((size_t)(nb*64 + kt)*16 + nsub)*64 + gr*8;
    *(uint4*)(out + base)     = make_uint4(arr[0], arr[1], arr[2], arr[3]);
    *(uint4*)(out + base + 4) = make_uint4(arr[4], arr[5], arr[6], arr[7]);
}

__global__ void zero_state_kernel(){
    int i = blockIdx.x * blockDim.x + threadIdx.x;
    if (i < B_*L_*D_) g_G[i] = 0.f;
    if (i < B_*L_)    g_Ksum[i] = 0.f;
}

// =============== GEMM core macro (BM=128,BN=128,BK=32, 3 stages, 128 thr) ====
#define GEMM_CORE(AB, BB, NITER)                                              \
    const int tid  = threadIdx.x;                                             \
    const int w    = tid >> 5;                                                \
    const int lane = tid & 31;                                                \
    const int wmsub = (w >> 1) * 4;                                           \
    const int wnsub = (w & 1) * 8;                                            \
    float c[4][8][4];                                                         \
    _Pragma("unroll")                                                         \
    for (int a_ = 0; a_ < 4; a_++)                                            \
        _Pragma("unroll")                                                     \
        for (int b_ = 0; b_ < 8; b_++)                                        \
            _Pragma("unroll")                                                 \
            for (int e_ = 0; e_ < 4; e_++) c[a_][b_][e_] = 0.f;               \
    {                                                                         \
        _Pragma("unroll")                                                     \
        for (int p = 0; p < 4; p++){                                          \
            cp16(As + p*128 + tid, AB + p*128 + tid);                         \
            cp16(Bs + p*128 + tid, BB + p*128 + tid);                         \
        }                                                                     \
        asm volatile("cp.async.commit_group;" ::: "memory");                  \
        _Pragma("unroll")                                                     \
        for (int p = 0; p < 4; p++){                                          \
            cp16(As + 512 + p*128 + tid, AB + 512 + p*128 + tid);             \
            cp16(Bs + 512 + p*128 + tid, BB + 512 + p*128 + tid);             \
        }                                                                     \
        asm volatile("cp.async.commit_group;" ::: "memory");                  \
    }                                                                         \
    int buf = 0;                                                              \
    for (int it = 0; it < (NITER); ++it){                                     \
        asm volatile("cp.async.wait_group 1;" ::: "memory");                  \
        __syncthreads();                                                      \
        _Pragma("unroll")                                                     \
        for (int ktl = 0; ktl < 2; ++ktl){                                    \
            const uint4* as = &As[buf*512 + ktl*256];                         \
            const uint4* bs = &Bs[buf*512 + ktl*256];                         \
            uint4 af[4]; uint2 bf[8];                                         \
            _Pragma("unroll")                                                 \
            for (int mi = 0; mi < 4; ++mi)                                    \
                af[mi] = as[(wmsub + mi)*32 + lane];                          \
            _Pragma("unroll")                                                 \
            for (int ni = 0; ni < 8; ++ni)                                    \
                bf[ni] = *(const uint2*)((const uint32_t*)bs                  \
                                         + (wnsub + ni)*64 + lane*2);         \
            _Pragma("unroll")                                                 \
            for (int mi = 0; mi < 4; ++mi)                                    \
                _Pragma("unroll")                                             \
                for (int ni = 0; ni < 8; ++ni)                                \
                    mma16(c[mi][ni], af[mi].x, af[mi].z, af[mi].y, af[mi].w,  \
                          bf[ni].x, bf[ni].y);                                \
        }                                                                     \
        if (it + 2 < (NITER)){                                                \
            int nbuf = buf + 2; if (nbuf >= 3) nbuf -= 3;                     \
            const uint4* sa = AB + (size_t)(it+2)*512;                        \
            const uint4* sb = BB + (size_t)(it+2)*512;                        \
            _Pragma("unroll")                                                 \
            for (int p = 0; p < 4; p++){                                      \
                cp16(As + nbuf*512 + p*128 + tid, sa + p*128 + tid);          \
                cp16(Bs + nbuf*512 + p*128 + tid, sb + p*128 + tid);          \
            }                                                                 \
        }                                                                     \
        asm volatile("cp.async.commit_group;" ::: "memory");                  \
        buf = (buf + 1 == 3) ? 0 : buf + 1;                                   \
    }

// ---------------- GEMM1: [K|Q] = X @ [Wk|Wq], fused epilogue -----------------
// nb==0: Em = exp(K)*mask -> fp16 E^T A-frag (smem-staged) + Ksum atomics
// nb==1: softmax(Q) -> fp16 A-frag (smem-staged)
__global__ __launch_bounds__(128)
void gemm1_kernel(const uint4* __restrict__ Apk, const uint4* __restrict__ Bpk,
                  const float* __restrict__ mask){
    __shared__ uint4 SM[3072];       // 48 KB: stages then staging buffer
    uint4* As = SM;
    uint4* Bs = SM + 1536;
    const int nb = blockIdx.x, mb = blockIdx.y;
    const uint4* Abase = Apk + (size_t)mb * 64 * 256;
    const uint4* Bbase = Bpk + (size_t)nb * 64 * 256;

    GEMM_CORE(Abase, Bbase, 32)

    const int gr = lane >> 2, gc = lane & 3;
    const int wm = (w >> 1) * 64, wn = (w & 1) * 64;
    const int b  = mb >> 6;
    __syncthreads();                 // smem reuse for staging

    unsigned short* sh = (unsigned short*)SM;
    uint32_t* sw = (uint32_t*)SM;

    if (nb == 0){
        const int gct = gr >> 1, par = gr & 1;
        float ks_e[8], ks_o[8];
        #pragma unroll
        for (int ni = 0; ni < 8; ++ni){ ks_e[ni] = 0.f; ks_o[ni] = 0.f; }
        #pragma unroll
        for (int mi = 0; mi < 4; ++mi){
            int t0 = mb*128 + wm + mi*16 + gr;
            float m0 = __ldg(mask + t0), m1 = __ldg(mask + t0 + 8);
            int ktl = (wm >> 4) + mi;
            #pragma unroll
            for (int ni = 0; ni < 8; ++ni){
                int cl = wn + ni*8 + gc*2;
                float v0 = __expf(c[mi][ni][0]) * m0;
                float v1 = __expf(c[mi][ni][1]) * m0;
                float v2 = __expf(c[mi][ni][2]) * m1;
                float v3 = __expf(c[mi][ni][3]) * m1;
                ks_e[ni] += v0 + v2;
                ks_o[ni] += v1 + v3;
                int ms0 = cl >> 4, hi0 = (cl >> 3) & 1, gh0 = cl & 7;
                int eb = (ktl*8 + ms0)*128 + gh0*16 + gct*4 + hi0*2;
                sh[(eb     )*2 + par] = __half_as_ushort(__float2half_rn(v0));
                sh[(eb + 16)*2 + par] = __half_as_ushort(__float2half_rn(v1));
                sh[(eb +  1)*2 + par] = __half_as_ushort(__float2half_rn(v2));
                sh[(eb + 17)*2 + par] = __half_as_ushort(__float2half_rn(v3));
            }
        }
        #pragma unroll
        for (int ni = 0; ni < 8; ++ni){
            float se = ks_e[ni], so = ks_o[ni];
            se += __shfl_xor_sync(0xffffffffu, se, 4);
            se += __shfl_xor_sync(0xffffffffu, se, 8);
            se += __shfl_xor_sync(0xffffffffu, se, 16);
            so += __shfl_xor_sync(0xffffffffu, so, 4);
            so += __shfl_xor_sync(0xffffffffu, so, 8);
            so += __shfl_xor_sync(0xffffffffu, so, 16);
            if (gr == 0){
                int cl = wn + ni*8 + gc*2;
                atomicAdd(&g_Ksum[b*128 + cl],     se);
                atomicAdd(&g_Ksum[b*128 + cl + 1], so);
            }
        }
        __syncthreads();
        uint4* dst = ((uint4*)g_ET) + ((size_t)b*512 + (mb & 63)*8)*256;
        #pragma unroll
        for (int i = 0; i < 16; ++i) dst[i*128 + tid] = SM[i*128 + tid];
    } else {
        #pragma unroll
        for (int mi = 0; mi < 4; ++mi){
            int msubt = ((wm >> 4) + mi) & 7;
            #pragma unroll
            for (int ni = 0; ni < 8; ++ni){
                int cl = wn + ni*8 + gc*2;
                float v0 = c[mi][ni][0], v1 = c[mi][ni][1];
                float v2 = c[mi][ni][2], v3 = c[mi][ni][3];
                float mx0 = fmaxf(v0, v1);
                mx0 = fmaxf(mx0, __shfl_xor_sync(0xffffffffu, mx0, 1));
                mx0 = fmaxf(mx0, __shfl_xor_sync(0xffffffffu, mx0, 2));
                float e0 = __expf(v0 - mx0), e1 = __expf(v1 - mx0);
                float s0 = e0 + e1;
                s0 += __shfl_xor_sync(0xffffffffu, s0, 1);
                s0 += __shfl_xor_sync(0xffffffffu, s0, 2);
                float i0 = 1.f / s0;
                float mx1 = fmaxf(v2, v3);
                mx1 = fmaxf(mx1, __shfl_xor_sync(0xffffffffu, mx1, 1));
                mx1 = fmaxf(mx1, __shfl_xor_sync(0xffffffffu, mx1, 2));
                float e2 = __expf(v2 - mx1), e3 = __expf(v3 - mx1);
                float s1 = e2 + e3;
                s1 += __shfl_xor_sync(0xffffffffu, s1, 1);
                s1 += __shfl_xor_sync(0xffffffffu, s1, 2);
                float i1 = 1.f / s1;
                int ktl = cl >> 4, k8 = ni & 1;
                int idx = (ktl*8 + msubt)*128 + (gr*4 + gc)*4 + k8;
                sw[idx]     = f2h2(e0*i0, e1*i0);
                sw[idx + 2] = f2h2(e2*i1, e3*i1);
            }
        }
        __syncthreads();
        uint4* dst = ((uint4*)g_Qs) + (size_t)mb*2048;
        #pragma unroll
        for (int i = 0; i < 16; ++i) dst[i*128 + tid] = SM[i*128 + tid];
    }
}

// ---------------- G += Em^T @ X  (split-K over t, fp32 atomics) --------------
__global__ __launch_bounds__(128)
void gemm_g_kernel(const uint4* __restrict__ Apk, const uint4* __restrict__ Bpk){
    __shared__ uint4 SM[3072];
    uint4* As = SM;
    uint4* Bs = SM + 1536;
    const int nb = blockIdx.x;                 // 0..7 (D blocks)
    const int b  = blockIdx.y >> 4, kc = blockIdx.y & 15;
    const uint4* Abase = Apk + ((size_t)b*512 + kc*32)*256;
    const uint4* Bbase = Bpk + (((size_t)(b*8 + nb)*512) + kc*32)*256;

    GEMM_CORE(Abase, Bbase, 16)

    const int gr = lane >> 2, gc = lane & 3;
    const int wm = (w >> 1) * 64, wn = (w & 1) * 64;
    #pragma unroll
    for (int mi = 0; mi < 4; ++mi){
        int hl = wm + mi*16 + gr;
        #pragma unroll
        for (int ni = 0; ni < 8; ++ni){
            int Dc = nb*128 + wn + ni*8 + gc*2;
            float* gp = &g_G[((size_t)b*128 + hl)*1024 + Dc];
            atomicAdd(gp,            c[mi][ni][0]);
            atomicAdd(gp + 1,        c[mi][ni][1]);
            atomicAdd(gp + 8*1024,   c[mi][ni][2]);
            atomicAdd(gp + 8*1024+1, c[mi][ni][3]);
        }
    }
}

// ---------------- Kv[b,h,l,d] = (G @ Wv_head) / Ksum -------------------------
__global__ __launch_bounds__(256)
void kvz1_kernel(const float* __restrict__ Wv){
    int bh = blockIdx.x;                // b*16 + h
    int b = bh >> 4, h = bh & 15;
    __shared__ float Gs[8][1024];       // 32 KB
    int tid = threadIdx.x;
    for (int i = tid; i < 8192; i += 256){
        int l = i >> 10, Dc = i & 1023;
        Gs[l][Dc] = g_G[((size_t)b*128 + h*8 + l)*1024 + Dc];
    }
    __syncthreads();
    int d = tid & 63, lg = tid >> 6;
    int l0 = lg*2, l1 = l0 + 1;
    float a0 = 0.f, a1 = 0.f;
    const float* wcol = Wv + h*64 + d;
    #pragma unroll 8
    for (int Dc = 0; Dc < 1024; ++Dc){
        float wv = __ldg(wcol + (size_t)Dc*1024);
        a0 += Gs[l0][Dc] * wv;
        a1 += Gs[l1][Dc] * wv;
    }
    g_Kv[(bh*8 + l0)*64 + d] = a0 / g_Ksum[b*128 + h*8 + l0];
    g_Kv[(bh*8 + l1)*64 + d] = a1 / g_Ksum[b*128 + h*8 + l1];
}

// ---------------- Z[b,(h,l),n] = sum_d Kv[b,h,l,d] * Po[h*64+d, n] -----------
__global__ __launch_bounds__(256)
void z_kernel(const float* __restrict__ Po){
    int bid = blockIdx.x;           // b*64 + h*4 + nc
    int b = bid >> 6, h = (bid >> 2) & 15, nc = bid & 3;
    int tid = threadIdx.x;

    __shared__ float kvn[8][64];
    for (int j = tid; j < 512; j += 256){
        int l = j >> 6, d = j & 63;
        kvn[l][d] = g_Kv[((b*16 + h)*8 + l)*64 + d];
    }
    __syncthreads();

    int n = nc*256 + tid;
    float acc[8];
    #pragma unroll
    for (int l = 0; l < 8; ++l) acc[l] = 0.f;
    for (int d = 0; d < 64; ++d){
        float po = __ldg(Po + (size_t)(h*64 + d)*1024 + n);
        #pragma unroll
        for (int l = 0; l < 8; ++l) acc[l] += kvn[l][d] * po;
    }

    int nbk = n >> 7, nsub = (n & 127) >> 3, gr = n & 7;
    int kt = h >> 1, k8 = h & 1;
    uint32_t* out = (uint32_t*)g_Z;
    size_t base = (((size_t)(b*8 + nbk)*8 + kt)*16 + nsub)*64 + gr*8 + k8;
    #pragma unroll
    for (int j2 = 0; j2 < 4; ++j2)
        out[base + j2*2] = f2h2(acc[2*j2], acc[2*j2+1]);
}

// ---------------- GEMM2: out = Qs @ Z_b  (K=128) -----------------------------
__global__ __launch_bounds__(128)
void gemm2_kernel(const uint4* __restrict__ Apk, const uint4* __restrict__ Bpk,
                  float* __restrict__ C){
    __shared__ uint4 SM[3072];
    uint4* As = SM;
    uint4* Bs = SM + 1536;
    const int nb = blockIdx.x, mb = blockIdx.y;
    const uint4* Abase = Apk + (size_t)mb * 8 * 256;
    const uint4* Bbase = Bpk + (size_t)(mb >> 6) * 16384
                             + (size_t)nb * 8 * 256;

    GEMM_CORE(Abase, Bbase, 4)

    const int gr = lane >> 2, gc = lane & 3;
    const int wm = (w >> 1) * 64, wn = (w & 1) * 64;
    #pragma unroll
    for (int mi = 0; mi < 4; ++mi){
        int r0 = mb*128 + wm + mi*16 + gr;
        #pragma unroll
        for (int ni = 0; ni < 8; ++ni){
            int c0 = nb*128 + wn + ni*8 + gc*2;
            *reinterpret_cast<float2*>(&C[(size_t)r0*D_ + c0])
                = make_float2(c[mi][ni][0], c[mi][ni][1]);
            *reinterpret_cast<float2*>(&C[(size_t)(r0+8)*D_ + c0])
                = make_float2(c[mi][ni][2], c[mi][ni][3]);
        }
    }
}

// ---------------- launch -----------------------------------------------------
extern "C" void kernel_launch(void* const* d_in, const int* in_sizes, int n_in,
                              void* d_out, int out_size){
    const float* X    = (const float*)d_in[0];
    const float* mask = (const float*)d_in[1];
    const float* Wk   = (const float*)d_in[2];
    const float* Wq   = (const float*)d_in[3];
    const float* Wv   = (const float*)d_in[4];
    const float* Po   = (const float*)d_in[5];
    float* out = (float*)d_out;

    void *pXpk, *pXT, *pWpk, *pET, *pQs, *pZ;
    cudaGetSymbolAddress(&pXpk, g_Xpk);
    cudaGetSymbolAddress(&pXT,  g_XT);
    cudaGetSymbolAddress(&pWpk, g_Wpk);
    cudaGetSymbolAddress(&pET,  g_ET);
    cudaGetSymbolAddress(&pQs,  g_Qs);
    cudaGetSymbolAddress(&pZ,   g_Z);

    pack_xc_kernel<<<(R_/16)*(D_/128), 256>>>(X);
    prep_w_kernel<<<64, 256>>>(Wk, Wq);
    zero_state_kernel<<<(B_*L_*D_ + 255)/256, 256>>>();

    gemm1_kernel<<<dim3(2, R_/128), 128>>>((const uint4*)pXpk,
                                           (const uint4*)pWpk, mask);

    gemm_g_kernel<<<dim3(8, B_*16), 128>>>((const uint4*)pET,
                                           (const uint4*)pXT);

    kvz1_kernel<<<B_*H_, 256>>>(Wv);
    z_kernel<<<B_*H_*4, 256>>>(Po);

    gemm2_kernel<<<dim3(8, R_/128), 128>>>((const uint4*)pQs,
                                           (const uint4*)pZ, out);
}